// round 14
// baseline (speedup 1.0000x reference)
#include <cuda_runtime.h>
#include <cuda_fp16.h>
#include <cstdint>

// ---------------- problem constants ----------------
#define E_DIM   768
#define B_SZ    8
#define NQ      8192
#define NBANK   20000
#define NPAD    20224          // 79 * 256
#define OUTS    512

#define M_TILE  128
#define N_TILE  256
#define NTN     79             // N tiles per mtile row
#define NMT     64             // mtiles (NQ / M_TILE)
#define TTOT    (NMT * NTN)    // 5056 global tiles
#define GCTA    148            // grid size == SM count
#define NHC     24             // K=32 chunks per tile

#define A_BYTES  (M_TILE * 128 * 12)       // 196608
#define B_SLICE  4096                      // 64 N-rows x 32 k-halves (macro-packed)
#define SMEM_DYN (A_BYTES + 4 * 2 * B_SLICE)   // 229376

// fused prep grid layout
#define PB_BLOCKS (NPAD / 8)               // 2528
#define PQ_BLOCKS (24 * 32 * 8)            // 6144
#define Q2_BLOCKS (32 * 8)                 // 256
#define PREP_GRID (PB_BLOCKS + PQ_BLOCKS + Q2_BLOCKS)

// ---------------- device scratch ----------------
__device__ __align__(256) __half g_q[NQ * E_DIM];
__device__ __align__(256) __half g_bank[(size_t)NPAD * E_DIM];
__device__ float g_q2[NQ];
__device__ float g_b2[NPAD];
__device__ float g_part[NQ * 4 * 3];       // up to 4 partial slots per query
__device__ float g_scores[NQ];

__host__ __device__ __forceinline__ int i_of_tile(int t) {
    return (t * GCTA + GCTA - 1) / TTOT;   // CTA owning global tile t
}

// ---------------- PTX helpers ----------------
__device__ __forceinline__ void cp_async16(uint32_t dst, const void* src) {
    asm volatile("cp.async.cg.shared.global [%0], [%1], 16;\n" :: "r"(dst), "l"(src));
}
__device__ __forceinline__ void cp_commit() { asm volatile("cp.async.commit_group;\n"); }
__device__ __forceinline__ void cp_wait0()  { asm volatile("cp.async.wait_group 0;\n"); }
__device__ __forceinline__ void bar_named(int id) {
    asm volatile("bar.sync %0, 128;" :: "r"(id) : "memory");
}

#define LDM4(r0, r1, r2, r3, addr)                                          \
    asm volatile("ldmatrix.sync.aligned.m8n8.x4.shared.b16 {%0,%1,%2,%3}, [%4];" \
                 : "=r"(r0), "=r"(r1), "=r"(r2), "=r"(r3) : "r"(addr))

// f16 x f16 -> f16 accumulate (2 packed-half2 C regs)
#define MMA16816H(c, a, b)                                                   \
    asm volatile("mma.sync.aligned.m16n8k16.row.col.f16.f16.f16.f16 "        \
                 "{%0,%1},{%2,%3,%4,%5},{%6,%7},{%0,%1};"                    \
                 : "+r"(c[0]), "+r"(c[1])                                    \
                 : "r"(a[0]), "r"(a[1]), "r"(a[2]), "r"(a[3]),               \
                   "r"(b[0]), "r"(b[1]))

__device__ __forceinline__ void upd3(float* t, float v) {
    if (v < t[2]) {
        if (v < t[1]) {
            t[2] = t[1];
            if (v < t[0]) { t[1] = t[0]; t[0] = v; } else t[1] = v;
        } else t[2] = v;
    }
}

// ---------------- fused prep: bank conv + q transpose + q2, one launch ----------------
__global__ void prep_fused_kernel(const float* __restrict__ emb,
                                  const float* __restrict__ bank) {
    __shared__ float t[32][33];            // used by q-transpose role
    __shared__ float red[8][32];           // used by q2 role
    int bid = blockIdx.x;
    if (bid < PB_BLOCKS) {
        // ---- bank -> f16 + ||b||^2 (warp/row, vectorized float4 -> half2) ----
        int w = threadIdx.x >> 5, lane = threadIdx.x & 31;
        int n = bid * 8 + w;
        if (n < NBANK) {
            const float4* src4 = (const float4*)(bank + (size_t)n * E_DIM);
            uint2* dst4 = (uint2*)(g_bank + (size_t)n * E_DIM);
            float ss = 0.f;
            #pragma unroll
            for (int i = 0; i < 6; i++) {
                float4 v = src4[lane + i * 32];
                ss = fmaf(v.x, v.x, fmaf(v.y, v.y, fmaf(v.z, v.z, fmaf(v.w, v.w, ss))));
                __half2 lo = __floats2half2_rn(v.x, v.y);
                __half2 hi = __floats2half2_rn(v.z, v.w);
                uint2 o;
                o.x = *(uint32_t*)&lo;
                o.y = *(uint32_t*)&hi;
                dst4[lane + i * 32] = o;
            }
            #pragma unroll
            for (int o = 16; o; o >>= 1) ss += __shfl_xor_sync(0xffffffffu, ss, o);
            if (lane == 0) g_b2[n] = ss;
        } else {
            uint2* dst4 = (uint2*)(g_bank + (size_t)n * E_DIM);
            #pragma unroll
            for (int i = 0; i < 6; i++) dst4[lane + i * 32] = make_uint2(0u, 0u);
            if (lane == 0) g_b2[n] = 1e30f;
        }
    } else if (bid < PB_BLOCKS + PQ_BLOCKS) {
        // ---- transpose emb [B,E,HW] -> g_q [B*HW][E] f16 ----
        int idx = bid - PB_BLOCKS;
        int e0 = (idx % 24) * 32;
        int hw0 = ((idx / 24) & 31) * 32;
        int b = idx / (24 * 32);
        int lx = threadIdx.x & 31, ly = threadIdx.x >> 5;
        const float* src = emb + ((size_t)b * E_DIM + e0) * 1024 + hw0;
        #pragma unroll
        for (int i = 0; i < 32; i += 8)
            t[ly + i][lx] = src[(size_t)(ly + i) * 1024 + lx];
        __syncthreads();
        __half* dst = g_q + (size_t)(b * 1024 + hw0) * E_DIM + e0;
        #pragma unroll
        for (int i = 0; i < 32; i += 8)
            dst[(size_t)(ly + i) * E_DIM + lx] = __float2half(t[lx][ly + i]);
    } else {
        // ---- ||q||^2 from original fp32 ----
        int idx = bid - PB_BLOCKS - PQ_BLOCKS;
        int b = idx >> 5;
        int hw = (idx & 31) * 32 + (threadIdx.x & 31);
        int ly = threadIdx.x >> 5, lx = threadIdx.x & 31;
        const float* src = emb + (size_t)b * E_DIM * 1024 + hw;
        float ss = 0.f;
        #pragma unroll 8
        for (int e = ly; e < E_DIM; e += 8) {
            float v = src[(size_t)e * 1024];
            ss = fmaf(v, v, ss);
        }
        red[ly][lx] = ss;
        __syncthreads();
        if (ly == 0) {
            float s = 0.f;
            #pragma unroll
            for (int j = 0; j < 8; j++) s += red[j][lx];
            g_q2[b * 1024 + hw] = s;
        }
    }
}

// ---------------- main: R13 + batched per-chunk LDSM issue ----------------
__global__ __launch_bounds__(512, 1) void knn_main_kernel() {
    extern __shared__ __align__(1024) unsigned char dsm[];
    uint32_t A_base;
    asm("{ .reg .u64 t; cvta.to.shared.u64 t, %1; cvt.u32.u64 %0, t; }"
        : "=r"(A_base) : "l"(dsm));
    uint32_t B_base = A_base + A_BYTES;

    int tid = threadIdx.x, warp = tid >> 5, lane = tid & 31;
    int wm = warp & 3, wn = warp >> 2;     // SMSP-interleaved barrier groups
    int g = lane >> 2, tg = lane & 3;

    int cta = blockIdx.x;
    int ts = (cta * TTOT) / GCTA;
    int te = ((cta + 1) * TTOT) / GCTA;
    int nhc_tot = (te - ts) * NHC;

    uint32_t slice0 = B_base + wn * (2 * B_SLICE);
    int gt = wm * 32 + lane;               // 0..127 within wn-group

    // hoisted B prefetch offsets (2 x 16B per thread per chunk)
    uint32_t pdst[2], psrc[2];
    #pragma unroll
    for (int q = 0; q < 2; q++) {
        int j = gt + q * 128;              // 0..255
        int mr = j >> 3, u = j & 7;        // macro-row 0..31, unit 0..7
        pdst[q] = (uint32_t)(mr * 128 + ((u * 16) ^ ((mr & 7) << 4)));
        psrc[q] = (uint32_t)((2 * mr + (u >> 2)) * E_DIM + (u & 3) * 8);
    }

    // ldmatrix addressing (identical to R10/R13)
    int m_id = lane >> 3, rr = lane & 7;
    int xm = rr << 4;
    int ar = wm * 32 + (m_id & 1) * 8 + rr;
    int a_cb0 = (m_id >> 1) * 16;
    uint32_t boff[4], bx2[4];
    {
        int brow0 = (m_id >> 1) * 8 + rr;
        int clb = (m_id & 1) * 16;
        #pragma unroll
        for (int bj = 0; bj < 4; bj++) {
            int row = brow0 + bj * 16;
            boff[bj] = (uint32_t)((row >> 1) * 128);
            bx2[bj] = (uint32_t)((((row & 1) << 6) ^ (((row >> 1) & 7) << 4)) ^ clb);
        }
    }

    float top3[4][3];
    #pragma unroll
    for (int j = 0; j < 4; j++)
        #pragma unroll
        for (int k = 0; k < 3; k++) top3[j][k] = 1e30f;

    int h = 0;                              // global chunk counter
    int lnt = ts % NTN, lsub = 1;           // prefetch pointer (ntile, sub-chunk)
    int t = ts;
    int first = 1;

    #pragma unroll 1
    while (t < te) {
        int mt = t / NTN;                   // current mtile
        int tend = (mt + 1) * NTN;
        if (tend > te) tend = te;

        // ---- (re)load A for this mtile (128 x 768 resident) ----
        {
            const __half* Qg = g_q + (size_t)mt * M_TILE * E_DIM;
            #pragma unroll
            for (int i = 0; i < 24; i++) {
                int c = tid + i * 512;
                int kb = c >> 10, rem = c & 1023, r = rem >> 3, u = rem & 7;
                cp_async16(A_base + kb * 16384 + r * 128 + ((u * 16) ^ ((r & 7) << 4)),
                           Qg + (size_t)r * E_DIM + kb * 64 + u * 8);
            }
            if (first) {
                const __half* src =
                    g_bank + (size_t)(lnt * N_TILE + wn * 64) * E_DIM;  // sub 0
                cp_async16(slice0 + pdst[0], src + psrc[0]);
                cp_async16(slice0 + pdst[1], src + psrc[1]);
            }
            cp_commit();
        }
        cp_wait0();
        __syncthreads();

        #pragma unroll 1
        for (int tile = t; tile < tend; tile++) {
            uint32_t acc[2][8][2];
            #pragma unroll
            for (int mi = 0; mi < 2; mi++)
                #pragma unroll
                for (int nj = 0; nj < 8; nj++) {
                    acc[mi][nj][0] = 0u;
                    acc[mi][nj][1] = 0u;
                }

            #pragma unroll 1
            for (int hc = 0; hc < NHC; hc++, h++) {
                int st = h & 1;
                cp_wait0();
                bar_named(1 + wn);
                if (h + 1 < nhc_tot) {
                    uint32_t dst = slice0 + ((h + 1) & 1) * B_SLICE;
                    const __half* src =
                        g_bank + (size_t)(lnt * N_TILE + wn * 64) * E_DIM + lsub * 32;
                    cp_async16(dst + pdst[0], src + psrc[0]);
                    cp_async16(dst + pdst[1], src + psrc[1]);
                    cp_commit();
                    if (++lsub == NHC) {
                        lsub = 0;
                        lnt = (lnt + 1 == NTN) ? 0 : lnt + 1;
                    }
                }

                uint32_t qb = A_base + (hc >> 1) * 16384;
                int acol0 = (hc & 1) * 64;
                uint32_t bb = slice0 + st * B_SLICE;

                // batched fragment loads: all 12 LDSM issued before any MMA,
                // so ks=1's smem latency hides under ks=0's MMA stream.
                uint32_t a[2][2][4];        // [ks][mi]
                uint32_t bf[2][8][2];       // [ks][nj]
                #pragma unroll
                for (int ks = 0; ks < 2; ks++) {
                    #pragma unroll
                    for (int mi = 0; mi < 2; mi++) {
                        uint32_t addr = qb + (uint32_t)((ar + mi * 16) * 128 +
                                            ((acol0 + ks * 32 + a_cb0) ^ xm));
                        LDM4(a[ks][mi][0], a[ks][mi][1], a[ks][mi][2], a[ks][mi][3], addr);
                    }
                    #pragma unroll
                    for (int bj = 0; bj < 4; bj++) {
                        uint32_t addr = bb + boff[bj] + (bx2[bj] ^ (ks << 5));
                        LDM4(bf[ks][2 * bj][0], bf[ks][2 * bj][1],
                             bf[ks][2 * bj + 1][0], bf[ks][2 * bj + 1][1], addr);
                    }
                }
                #pragma unroll
                for (int ks = 0; ks < 2; ks++)
                    #pragma unroll
                    for (int mi = 0; mi < 2; mi++)
                        #pragma unroll
                        for (int nj = 0; nj < 8; nj++)
                            MMA16816H(acc[mi][nj], a[ks][mi], bf[ks][nj]);
            }

            // epilogue: rank (b2 - 2*dot); q2 added in finalize
            int nb = (tile - mt * NTN) * N_TILE + wn * 64;
            #pragma unroll
            for (int nj = 0; nj < 8; nj++) {
                int cb = nb + nj * 8 + tg * 2;
                float b2a = __ldg(g_b2 + cb), b2b = __ldg(g_b2 + cb + 1);
                #pragma unroll
                for (int mi = 0; mi < 2; mi++) {
                    float2 d0 = __half22float2(*(__half2*)&acc[mi][nj][0]); // row g
                    float2 d1 = __half22float2(*(__half2*)&acc[mi][nj][1]); // row g+8
                    upd3(top3[mi * 2],     fmaf(-2.f, d0.x, b2a));
                    upd3(top3[mi * 2],     fmaf(-2.f, d0.y, b2b));
                    upd3(top3[mi * 2 + 1], fmaf(-2.f, d1.x, b2a));
                    upd3(top3[mi * 2 + 1], fmaf(-2.f, d1.y, b2b));
                }
            }
        }

        // ---- mtile segment done: merge 16 partials/row, write slot ----
        __syncthreads();
        float* mrg = (float*)dsm;          // reuses A region (reloaded next seg)
        int slot16 = wn * 4 + tg;
        #pragma unroll
        for (int j = 0; j < 4; j++) {
            int row = wm * 32 + (j >> 1) * 16 + (j & 1) * 8 + g;
            #pragma unroll
            for (int k = 0; k < 3; k++) mrg[(row * 16 + slot16) * 3 + k] = top3[j][k];
        }
        __syncthreads();
        if (tid < M_TILE) {
            float t0v = 1e30f, t1v = 1e30f, t2v = 1e30f;
            const float* p = mrg + tid * 48;
            #pragma unroll
            for (int i = 0; i < 48; i++) {
                float v = p[i];
                if (v < t2v) {
                    if (v < t1v) { t2v = t1v; if (v < t0v) { t1v = t0v; t0v = v; } else t1v = v; }
                    else t2v = v;
                }
            }
            int q = mt * M_TILE + tid;
            int slot = cta - i_of_tile(mt * NTN);
            float* o = g_part + (q * 4 + slot) * 3;
            o[0] = t0v; o[1] = t1v; o[2] = t2v;
        }
        __syncthreads();                   // protect mrg before next A reload

        #pragma unroll
        for (int j = 0; j < 4; j++)
            #pragma unroll
            for (int k = 0; k < 3; k++) top3[j][k] = 1e30f;
        t = tend;
        first = 0;
    }
}

// ---------------- finalize: merge valid slots, sqrt-mean ----------------
__global__ void finalize_kernel() {
    int q = blockIdx.x * blockDim.x + threadIdx.x;
    if (q >= NQ) return;
    int mt = q >> 7;
    int i_f = i_of_tile(mt * NTN);
    int i_l = i_of_tile(mt * NTN + NTN - 1);
    int nsl = i_l - i_f + 1;               // 1..4
    float t0 = 1e30f, t1 = 1e30f, t2 = 1e30f;
    const float* p = g_part + q * 4 * 3;
    for (int i = 0; i < nsl * 3; i++) {
        float v = p[i];
        if (v < t2) {
            if (v < t1) { t2 = t1; if (v < t0) { t1 = t0; t0 = v; } else t1 = v; }
            else t2 = v;
        }
    }
    float q2 = g_q2[q];
    float s = (sqrtf(fmaxf(q2 + t0, 1e-12f)) +
               sqrtf(fmaxf(q2 + t1, 1e-12f)) +
               sqrtf(fmaxf(q2 + t2, 1e-12f))) * (1.f / 3.f);
    g_scores[q] = s;
}

// ---------------- bilinear 32 -> 512, 4 px per thread ----------------
__global__ void resize_kernel(float* __restrict__ out) {
    int idx = blockIdx.x * 256 + threadIdx.x;        // 512K quads
    if (idx >= B_SZ * OUTS * (OUTS / 4)) return;
    int xq = idx & (OUTS / 4 - 1);                   // quad index in row
    int y = (idx >> 7) & (OUTS - 1);
    int b = idx >> 16;
    float sy = (y + 0.5f) * (1.0f / 16.0f) - 0.5f;
    float fy0 = floorf(sy);
    float ay = sy - fy0;
    int iy0 = (int)fy0;
    int y0 = max(0, min(31, iy0)), y1 = max(0, min(31, iy0 + 1));
    const float* s = g_scores + b * 1024;
    const float* r0 = s + y0 * 32;
    const float* r1 = s + y1 * 32;
    float4 res;
    float* rp = (float*)&res;
    #pragma unroll
    for (int i = 0; i < 4; i++) {
        int x = xq * 4 + i;
        float sx = (x + 0.5f) * (1.0f / 16.0f) - 0.5f;
        float fx0 = floorf(sx);
        float ax = sx - fx0;
        int ix0 = (int)fx0;
        int x0 = max(0, min(31, ix0)), x1 = max(0, min(31, ix0 + 1));
        float v0 = r0[x0] + ax * (r0[x1] - r0[x0]);
        float v1 = r1[x0] + ax * (r1[x1] - r1[x0]);
        rp[i] = v0 + ay * (v1 - v0);
    }
    ((float4*)out)[idx] = res;
}

// ---------------- launch ----------------
extern "C" void kernel_launch(void* const* d_in, const int* in_sizes, int n_in,
                              void* d_out, int out_size) {
    const float* emb = (const float*)d_in[0];
    const float* bank = (n_in > 1) ? (const float*)d_in[1] : nullptr;
    for (int i = 0; i < n_in; i++) {
        if (in_sizes[i] == B_SZ * E_DIM * 1024) emb = (const float*)d_in[i];
        else if (in_sizes[i] == NBANK * E_DIM)  bank = (const float*)d_in[i];
    }

    prep_fused_kernel<<<PREP_GRID, 256>>>(emb, bank);

    cudaFuncSetAttribute(knn_main_kernel,
                         cudaFuncAttributeMaxDynamicSharedMemorySize, SMEM_DYN);
    knn_main_kernel<<<GCTA, 512, SMEM_DYN>>>();

    finalize_kernel<<<NQ / 256, 256>>>();
    resize_kernel<<<(B_SZ * OUTS * OUTS / 4) / 256, 256>>>((float*)d_out);
}

// round 15
// speedup vs baseline: 1.0459x; 1.0459x over previous
#include <cuda_runtime.h>
#include <cuda_fp16.h>
#include <cstdint>

// ---------------- problem constants ----------------
#define E_DIM   768
#define B_SZ    8
#define NQ      8192
#define NBANK   20000
#define NPAD    20224          // 79 * 256
#define OUTS    512

#define M_TILE  128
#define N_TILE  256
#define NTN     79             // N tiles per mtile row
#define NMT     64             // mtiles (NQ / M_TILE)
#define TTOT    (NMT * NTN)    // 5056 global tiles
#define GCTA    148            // grid size == SM count
#define NHC     24             // K=32 chunks per tile

#define A_BYTES  (M_TILE * 128 * 12)       // 196608
#define B_SLICE  4096                      // 64 N-rows x 32 k-halves (macro-packed)
#define SMEM_DYN (A_BYTES + 4 * 2 * B_SLICE)   // 229376

// fused prep grid layout
#define PB_BLOCKS (NPAD / 8)               // 2528
#define PQ_BLOCKS (24 * 32 * 8)            // 6144
#define Q2_BLOCKS (32 * 8)                 // 256
#define PREP_GRID (PB_BLOCKS + PQ_BLOCKS + Q2_BLOCKS)

// ---------------- device scratch ----------------
__device__ __align__(256) __half g_q[NQ * E_DIM];
__device__ __align__(256) __half g_bank[(size_t)NPAD * E_DIM];
__device__ float g_q2[NQ];
__device__ float g_b2[NPAD];
__device__ float g_part[NQ * 4 * 3];       // up to 4 partial slots per query
__device__ float g_scores[NQ];

__host__ __device__ __forceinline__ int i_of_tile(int t) {
    return (t * GCTA + GCTA - 1) / TTOT;   // CTA owning global tile t
}

// ---------------- PTX helpers ----------------
__device__ __forceinline__ void cp_async16(uint32_t dst, const void* src) {
    asm volatile("cp.async.cg.shared.global [%0], [%1], 16;\n" :: "r"(dst), "l"(src));
}
__device__ __forceinline__ void cp_commit() { asm volatile("cp.async.commit_group;\n"); }
__device__ __forceinline__ void cp_wait0()  { asm volatile("cp.async.wait_group 0;\n"); }
__device__ __forceinline__ void bar_named(int id) {
    asm volatile("bar.sync %0, 128;" :: "r"(id) : "memory");
}

#define LDM4(r0, r1, r2, r3, addr)                                          \
    asm volatile("ldmatrix.sync.aligned.m8n8.x4.shared.b16 {%0,%1,%2,%3}, [%4];" \
                 : "=r"(r0), "=r"(r1), "=r"(r2), "=r"(r3) : "r"(addr))

// f16 x f16 -> f16 accumulate (2 packed-half2 C regs)
#define MMA16816H(c, a, b)                                                   \
    asm volatile("mma.sync.aligned.m16n8k16.row.col.f16.f16.f16.f16 "        \
                 "{%0,%1},{%2,%3,%4,%5},{%6,%7},{%0,%1};"                    \
                 : "+r"(c[0]), "+r"(c[1])                                    \
                 : "r"(a[0]), "r"(a[1]), "r"(a[2]), "r"(a[3]),               \
                   "r"(b[0]), "r"(b[1]))

__device__ __forceinline__ void upd3(float* t, float v) {
    if (v < t[2]) {
        if (v < t[1]) {
            t[2] = t[1];
            if (v < t[0]) { t[1] = t[0]; t[0] = v; } else t[1] = v;
        } else t[2] = v;
    }
}

// ---------------- fused prep: bank conv + q transpose + q2, one launch ----------------
__global__ void prep_fused_kernel(const float* __restrict__ emb,
                                  const float* __restrict__ bank) {
    __shared__ float t[32][33];            // used by q-transpose role
    __shared__ float red[8][32];           // used by q2 role
    int bid = blockIdx.x;
    if (bid < PB_BLOCKS) {
        // ---- bank -> f16 + ||b||^2 (warp/row, vectorized float4 -> half2) ----
        int w = threadIdx.x >> 5, lane = threadIdx.x & 31;
        int n = bid * 8 + w;
        if (n < NBANK) {
            const float4* src4 = (const float4*)(bank + (size_t)n * E_DIM);
            uint2* dst4 = (uint2*)(g_bank + (size_t)n * E_DIM);
            float ss = 0.f;
            #pragma unroll
            for (int i = 0; i < 6; i++) {
                float4 v = src4[lane + i * 32];
                ss = fmaf(v.x, v.x, fmaf(v.y, v.y, fmaf(v.z, v.z, fmaf(v.w, v.w, ss))));
                __half2 lo = __floats2half2_rn(v.x, v.y);
                __half2 hi = __floats2half2_rn(v.z, v.w);
                uint2 o;
                o.x = *(uint32_t*)&lo;
                o.y = *(uint32_t*)&hi;
                dst4[lane + i * 32] = o;
            }
            #pragma unroll
            for (int o = 16; o; o >>= 1) ss += __shfl_xor_sync(0xffffffffu, ss, o);
            if (lane == 0) g_b2[n] = ss;
        } else {
            uint2* dst4 = (uint2*)(g_bank + (size_t)n * E_DIM);
            #pragma unroll
            for (int i = 0; i < 6; i++) dst4[lane + i * 32] = make_uint2(0u, 0u);
            if (lane == 0) g_b2[n] = 1e30f;
        }
    } else if (bid < PB_BLOCKS + PQ_BLOCKS) {
        // ---- transpose emb [B,E,HW] -> g_q [B*HW][E] f16 ----
        int idx = bid - PB_BLOCKS;
        int e0 = (idx % 24) * 32;
        int hw0 = ((idx / 24) & 31) * 32;
        int b = idx / (24 * 32);
        int lx = threadIdx.x & 31, ly = threadIdx.x >> 5;
        const float* src = emb + ((size_t)b * E_DIM + e0) * 1024 + hw0;
        #pragma unroll
        for (int i = 0; i < 32; i += 8)
            t[ly + i][lx] = src[(size_t)(ly + i) * 1024 + lx];
        __syncthreads();
        __half* dst = g_q + (size_t)(b * 1024 + hw0) * E_DIM + e0;
        #pragma unroll
        for (int i = 0; i < 32; i += 8)
            dst[(size_t)(ly + i) * E_DIM + lx] = __float2half(t[lx][ly + i]);
    } else {
        // ---- ||q||^2 from original fp32 ----
        int idx = bid - PB_BLOCKS - PQ_BLOCKS;
        int b = idx >> 5;
        int hw = (idx & 31) * 32 + (threadIdx.x & 31);
        int ly = threadIdx.x >> 5, lx = threadIdx.x & 31;
        const float* src = emb + (size_t)b * E_DIM * 1024 + hw;
        float ss = 0.f;
        #pragma unroll 8
        for (int e = ly; e < E_DIM; e += 8) {
            float v = src[(size_t)e * 1024];
            ss = fmaf(v, v, ss);
        }
        red[ly][lx] = ss;
        __syncthreads();
        if (ly == 0) {
            float s = 0.f;
            #pragma unroll
            for (int j = 0; j < 8; j++) s += red[j][lx];
            g_q2[b * 1024 + hw] = s;
        }
    }
}

// ---------------- main: EXACT R13 champion (f16-acc, no LDSM batching) ----------------
__global__ __launch_bounds__(512, 1) void knn_main_kernel() {
    extern __shared__ __align__(1024) unsigned char dsm[];
    uint32_t A_base;
    asm("{ .reg .u64 t; cvta.to.shared.u64 t, %1; cvt.u32.u64 %0, t; }"
        : "=r"(A_base) : "l"(dsm));
    uint32_t B_base = A_base + A_BYTES;

    int tid = threadIdx.x, warp = tid >> 5, lane = tid & 31;
    int wm = warp & 3, wn = warp >> 2;     // SMSP-interleaved barrier groups
    int g = lane >> 2, tg = lane & 3;

    int cta = blockIdx.x;
    int ts = (cta * TTOT) / GCTA;
    int te = ((cta + 1) * TTOT) / GCTA;
    int nhc_tot = (te - ts) * NHC;

    uint32_t slice0 = B_base + wn * (2 * B_SLICE);
    int gt = wm * 32 + lane;               // 0..127 within wn-group

    // hoisted B prefetch offsets (2 x 16B per thread per chunk)
    uint32_t pdst[2], psrc[2];
    #pragma unroll
    for (int q = 0; q < 2; q++) {
        int j = gt + q * 128;              // 0..255
        int mr = j >> 3, u = j & 7;        // macro-row 0..31, unit 0..7
        pdst[q] = (uint32_t)(mr * 128 + ((u * 16) ^ ((mr & 7) << 4)));
        psrc[q] = (uint32_t)((2 * mr + (u >> 2)) * E_DIM + (u & 3) * 8);
    }

    // ldmatrix addressing (identical to R10/R13)
    int m_id = lane >> 3, rr = lane & 7;
    int xm = rr << 4;
    int ar = wm * 32 + (m_id & 1) * 8 + rr;
    int a_cb0 = (m_id >> 1) * 16;
    uint32_t boff[4], bx2[4];
    {
        int brow0 = (m_id >> 1) * 8 + rr;
        int clb = (m_id & 1) * 16;
        #pragma unroll
        for (int bj = 0; bj < 4; bj++) {
            int row = brow0 + bj * 16;
            boff[bj] = (uint32_t)((row >> 1) * 128);
            bx2[bj] = (uint32_t)((((row & 1) << 6) ^ (((row >> 1) & 7) << 4)) ^ clb);
        }
    }

    float top3[4][3];
    #pragma unroll
    for (int j = 0; j < 4; j++)
        #pragma unroll
        for (int k = 0; k < 3; k++) top3[j][k] = 1e30f;

    int h = 0;                              // global chunk counter
    int lnt = ts % NTN, lsub = 1;           // prefetch pointer (ntile, sub-chunk)
    int t = ts;
    int first = 1;

    #pragma unroll 1
    while (t < te) {
        int mt = t / NTN;                   // current mtile
        int tend = (mt + 1) * NTN;
        if (tend > te) tend = te;

        // ---- (re)load A for this mtile (128 x 768 resident) ----
        {
            const __half* Qg = g_q + (size_t)mt * M_TILE * E_DIM;
            #pragma unroll
            for (int i = 0; i < 24; i++) {
                int c = tid + i * 512;
                int kb = c >> 10, rem = c & 1023, r = rem >> 3, u = rem & 7;
                cp_async16(A_base + kb * 16384 + r * 128 + ((u * 16) ^ ((r & 7) << 4)),
                           Qg + (size_t)r * E_DIM + kb * 64 + u * 8);
            }
            if (first) {
                const __half* src =
                    g_bank + (size_t)(lnt * N_TILE + wn * 64) * E_DIM;  // sub 0
                cp_async16(slice0 + pdst[0], src + psrc[0]);
                cp_async16(slice0 + pdst[1], src + psrc[1]);
            }
            cp_commit();
        }
        cp_wait0();
        __syncthreads();

        #pragma unroll 1
        for (int tile = t; tile < tend; tile++) {
            uint32_t acc[2][8][2];
            #pragma unroll
            for (int mi = 0; mi < 2; mi++)
                #pragma unroll
                for (int nj = 0; nj < 8; nj++) {
                    acc[mi][nj][0] = 0u;
                    acc[mi][nj][1] = 0u;
                }

            #pragma unroll 1
            for (int hc = 0; hc < NHC; hc++, h++) {
                int st = h & 1;
                cp_wait0();
                bar_named(1 + wn);
                if (h + 1 < nhc_tot) {
                    uint32_t dst = slice0 + ((h + 1) & 1) * B_SLICE;
                    const __half* src =
                        g_bank + (size_t)(lnt * N_TILE + wn * 64) * E_DIM + lsub * 32;
                    cp_async16(dst + pdst[0], src + psrc[0]);
                    cp_async16(dst + pdst[1], src + psrc[1]);
                    cp_commit();
                    if (++lsub == NHC) {
                        lsub = 0;
                        lnt = (lnt + 1 == NTN) ? 0 : lnt + 1;
                    }
                }

                uint32_t qb = A_base + (hc >> 1) * 16384;
                int acol0 = (hc & 1) * 64;
                uint32_t bb = slice0 + st * B_SLICE;
                #pragma unroll
                for (int ks = 0; ks < 2; ks++) {
                    uint32_t a[2][4];
                    #pragma unroll
                    for (int mi = 0; mi < 2; mi++) {
                        uint32_t addr = qb + (uint32_t)((ar + mi * 16) * 128 +
                                            ((acol0 + ks * 32 + a_cb0) ^ xm));
                        LDM4(a[mi][0], a[mi][1], a[mi][2], a[mi][3], addr);
                    }
                    uint32_t bf[8][2];
                    #pragma unroll
                    for (int bj = 0; bj < 4; bj++) {
                        uint32_t addr = bb + boff[bj] + (bx2[bj] ^ (ks << 5));
                        LDM4(bf[2 * bj][0], bf[2 * bj][1],
                             bf[2 * bj + 1][0], bf[2 * bj + 1][1], addr);
                    }
                    #pragma unroll
                    for (int mi = 0; mi < 2; mi++)
                        #pragma unroll
                        for (int nj = 0; nj < 8; nj++)
                            MMA16816H(acc[mi][nj], a[mi], bf[nj]);
                }
            }

            // epilogue: rank (b2 - 2*dot); q2 added in finalize
            int nb = (tile - mt * NTN) * N_TILE + wn * 64;
            #pragma unroll
            for (int nj = 0; nj < 8; nj++) {
                int cb = nb + nj * 8 + tg * 2;
                float b2a = __ldg(g_b2 + cb), b2b = __ldg(g_b2 + cb + 1);
                #pragma unroll
                for (int mi = 0; mi < 2; mi++) {
                    float2 d0 = __half22float2(*(__half2*)&acc[mi][nj][0]); // row g
                    float2 d1 = __half22float2(*(__half2*)&acc[mi][nj][1]); // row g+8
                    upd3(top3[mi * 2],     fmaf(-2.f, d0.x, b2a));
                    upd3(top3[mi * 2],     fmaf(-2.f, d0.y, b2b));
                    upd3(top3[mi * 2 + 1], fmaf(-2.f, d1.x, b2a));
                    upd3(top3[mi * 2 + 1], fmaf(-2.f, d1.y, b2b));
                }
            }
        }

        // ---- mtile segment done: merge 16 partials/row, write slot ----
        __syncthreads();
        float* mrg = (float*)dsm;          // reuses A region (reloaded next seg)
        int slot16 = wn * 4 + tg;
        #pragma unroll
        for (int j = 0; j < 4; j++) {
            int row = wm * 32 + (j >> 1) * 16 + (j & 1) * 8 + g;
            #pragma unroll
            for (int k = 0; k < 3; k++) mrg[(row * 16 + slot16) * 3 + k] = top3[j][k];
        }
        __syncthreads();
        if (tid < M_TILE) {
            float t0v = 1e30f, t1v = 1e30f, t2v = 1e30f;
            const float* p = mrg + tid * 48;
            #pragma unroll
            for (int i = 0; i < 48; i++) {
                float v = p[i];
                if (v < t2v) {
                    if (v < t1v) { t2v = t1v; if (v < t0v) { t1v = t0v; t0v = v; } else t1v = v; }
                    else t2v = v;
                }
            }
            int q = mt * M_TILE + tid;
            int slot = cta - i_of_tile(mt * NTN);
            float* o = g_part + (q * 4 + slot) * 3;
            o[0] = t0v; o[1] = t1v; o[2] = t2v;
        }
        __syncthreads();                   // protect mrg before next A reload

        #pragma unroll
        for (int j = 0; j < 4; j++)
            #pragma unroll
            for (int k = 0; k < 3; k++) top3[j][k] = 1e30f;
        t = tend;
        first = 0;
    }
}

// ---------------- finalize: merge valid slots, sqrt-mean ----------------
__global__ void finalize_kernel() {
    int q = blockIdx.x * blockDim.x + threadIdx.x;
    if (q >= NQ) return;
    int mt = q >> 7;
    int i_f = i_of_tile(mt * NTN);
    int i_l = i_of_tile(mt * NTN + NTN - 1);
    int nsl = i_l - i_f + 1;               // 1..4
    float t0 = 1e30f, t1 = 1e30f, t2 = 1e30f;
    const float* p = g_part + q * 4 * 3;
    for (int i = 0; i < nsl * 3; i++) {
        float v = p[i];
        if (v < t2) {
            if (v < t1) { t2 = t1; if (v < t0) { t1 = t0; t0 = v; } else t1 = v; }
            else t2 = v;
        }
    }
    float q2 = g_q2[q];
    float s = (sqrtf(fmaxf(q2 + t0, 1e-12f)) +
               sqrtf(fmaxf(q2 + t1, 1e-12f)) +
               sqrtf(fmaxf(q2 + t2, 1e-12f))) * (1.f / 3.f);
    g_scores[q] = s;
}

// ---------------- bilinear 32 -> 512, 4 px per thread ----------------
__global__ void resize_kernel(float* __restrict__ out) {
    int idx = blockIdx.x * 256 + threadIdx.x;        // quads
    if (idx >= B_SZ * OUTS * (OUTS / 4)) return;
    int xq = idx & (OUTS / 4 - 1);                   // quad index in row
    int y = (idx >> 7) & (OUTS - 1);
    int b = idx >> 16;
    float sy = (y + 0.5f) * (1.0f / 16.0f) - 0.5f;
    float fy0 = floorf(sy);
    float ay = sy - fy0;
    int iy0 = (int)fy0;
    int y0 = max(0, min(31, iy0)), y1 = max(0, min(31, iy0 + 1));
    const float* s = g_scores + b * 1024;
    const float* r0 = s + y0 * 32;
    const float* r1 = s + y1 * 32;
    float4 res;
    float* rp = (float*)&res;
    #pragma unroll
    for (int i = 0; i < 4; i++) {
        int x = xq * 4 + i;
        float sx = (x + 0.5f) * (1.0f / 16.0f) - 0.5f;
        float fx0 = floorf(sx);
        float ax = sx - fx0;
        int ix0 = (int)fx0;
        int x0 = max(0, min(31, ix0)), x1 = max(0, min(31, ix0 + 1));
        float v0 = r0[x0] + ax * (r0[x1] - r0[x0]);
        float v1 = r1[x0] + ax * (r1[x1] - r1[x0]);
        rp[i] = v0 + ay * (v1 - v0);
    }
    ((float4*)out)[idx] = res;
}

// ---------------- launch ----------------
extern "C" void kernel_launch(void* const* d_in, const int* in_sizes, int n_in,
                              void* d_out, int out_size) {
    const float* emb = (const float*)d_in[0];
    const float* bank = (n_in > 1) ? (const float*)d_in[1] : nullptr;
    for (int i = 0; i < n_in; i++) {
        if (in_sizes[i] == B_SZ * E_DIM * 1024) emb = (const float*)d_in[i];
        else if (in_sizes[i] == NBANK * E_DIM)  bank = (const float*)d_in[i];
    }

    prep_fused_kernel<<<PREP_GRID, 256>>>(emb, bank);

    cudaFuncSetAttribute(knn_main_kernel,
                         cudaFuncAttributeMaxDynamicSharedMemorySize, SMEM_DYN);
    knn_main_kernel<<<GCTA, 512, SMEM_DYN>>>();

    finalize_kernel<<<NQ / 256, 256>>>();
    resize_kernel<<<(B_SZ * OUTS * OUTS / 4) / 256, 256>>>((float*)d_out);
}